// round 14
// baseline (speedup 1.0000x reference)
#include <cuda_runtime.h>
#include <cuda_fp16.h>
#include <math.h>
#include <stdint.h>

// Problem constants
#define NB   2
#define SEQ  2048
#define HID  4096
#define NH   32
#define NKV  8
#define HD   128
#define QKVO ((NH + 2*NKV)*HD)   // 6144
#define MTOK (NB*SEQ)            // 4096

// Scratch
__device__ float g_qkv[(size_t)MTOK * QKVO];
__device__ __half g_ah[(size_t)MTOK * HID];
__device__ __half g_wh[(size_t)QKVO * HID];
__device__ __half g_qhh[(size_t)NB * NH * SEQ * HD];
__device__ __half g_qll[(size_t)NB * NH * SEQ * HD];
__device__ __half g_kk[(size_t)NB * NKV * SEQ * HD];
__device__ __half g_vv[(size_t)NB * NKV * SEQ * HD];
__device__ float2 g_rope[(size_t)SEQ * 64];

// ===========================================================================
// Low-level helpers
// ===========================================================================
__device__ __forceinline__ uint32_t smem_to_u32(const void* p) {
    uint32_t a;
    asm("{ .reg .u64 t; cvta.to.shared.u64 t, %1; cvt.u32.u64 %0, t; }" : "=r"(a) : "l"(p));
    return a;
}
__device__ __forceinline__ void ldsm_x4(uint32_t& r0, uint32_t& r1, uint32_t& r2,
                                        uint32_t& r3, uint32_t addr) {
    asm volatile("ldmatrix.sync.aligned.m8n8.x4.shared.b16 {%0,%1,%2,%3}, [%4];"
                 : "=r"(r0), "=r"(r1), "=r"(r2), "=r"(r3) : "r"(addr));
}
__device__ __forceinline__ void ldsm_x4_t(uint32_t& r0, uint32_t& r1, uint32_t& r2,
                                          uint32_t& r3, uint32_t addr) {
    asm volatile("ldmatrix.sync.aligned.m8n8.x4.trans.shared.b16 {%0,%1,%2,%3}, [%4];"
                 : "=r"(r0), "=r"(r1), "=r"(r2), "=r"(r3) : "r"(addr));
}
__device__ __forceinline__ void mma_fp16(float* c, uint32_t a0, uint32_t a1,
                                         uint32_t a2, uint32_t a3,
                                         uint32_t b0, uint32_t b1) {
    asm volatile(
        "mma.sync.aligned.m16n8k16.row.col.f32.f16.f16.f32 "
        "{%0,%1,%2,%3}, {%4,%5,%6,%7}, {%8,%9}, {%0,%1,%2,%3};"
        : "+f"(c[0]), "+f"(c[1]), "+f"(c[2]), "+f"(c[3])
        : "r"(a0), "r"(a1), "r"(a2), "r"(a3), "r"(b0), "r"(b1));
}
__device__ __forceinline__ void cpa16(uint32_t dst, const void* src) {
    asm volatile("cp.async.cg.shared.global [%0], [%1], 16;" :: "r"(dst), "l"(src));
}
#define CP_COMMIT() asm volatile("cp.async.commit_group;" ::: "memory")
#define CP_WAIT0()  asm volatile("cp.async.wait_group 0;" ::: "memory")
#define CP_WAIT1()  asm volatile("cp.async.wait_group 1;" ::: "memory")

__device__ __forceinline__ uint32_t pack2_fp16(float a, float b) {
    __half2 t = __floats2half2_rn(a, b);
    return *reinterpret_cast<uint32_t*>(&t);
}

// ===========================================================================
// RoPE table (fp64 once)
// ===========================================================================
__global__ void __launch_bounds__(256) rope_table_kernel(const int* __restrict__ positions)
{
    const int idx = blockIdx.x * 256 + threadIdx.x;
    if (idx >= SEQ * 64) return;
    const int s = idx >> 6, i = idx & 63;
    const int pos = positions[s];
    const double inv = exp(-(double)i * (9.210340371976184 / 64.0));
    double sd, cd;
    sincos((double)pos * inv, &sd, &cd);
    g_rope[idx] = make_float2((float)cd, (float)sd);
}

// ===========================================================================
// Conversions
// ===========================================================================
__global__ void __launch_bounds__(256) conv_fp16_kernel(
    const float* __restrict__ x, __half* __restrict__ hi, size_t n)
{
    size_t i = ((size_t)blockIdx.x * 256 + threadIdx.x) * 4;
    if (i >= n) return;
    float4 v = *(const float4*)(x + i);
    __half h[4] = { __float2half_rn(v.x), __float2half_rn(v.y),
                    __float2half_rn(v.z), __float2half_rn(v.w) };
    *(uint2*)(hi + i) = *(uint2*)h;
}

// ===========================================================================
// Shared GEMM geometry: 128B-row XOR-swizzled tiles
// ===========================================================================
#define GK 64
#define GTILE 16384                  // 128 rows * 128 B
#define NPERS 296                    // persistent grid: 2 CTAs x 148 SMs

__device__ __forceinline__ uint32_t gsw(int row, int seg) {
    return (uint32_t)(row * 128 + ((seg ^ row) & 7) * 16);
}

// ===========================================================================
// Persistent fp16x1 GEMM-NT: C = Ah * Bh^T.
// 296 CTAs loop over 128x128 tiles; 3-stage pipeline per tile; 2 CTAs/SM.
// ===========================================================================
#define G1STAGE (2 * GTILE)          // Ah, Bh = 32768 B
#define GEMM1_SMEM (3 * G1STAGE)     // 98304 B

__global__ void __launch_bounds__(256, 2) gemm_fp16x1_kernel(
    const __half* __restrict__ Ah, const __half* __restrict__ Bh,
    float* __restrict__ C, int M, int N, int K)
{
    extern __shared__ char smem[];
    const uint32_t sb = smem_to_u32(smem);
    const int tid  = threadIdx.x;
    const int wid  = tid >> 5;
    const int lane = tid & 31;
    const int warp_m = wid >> 2;
    const int warp_n = wid & 3;

    const int nx = N >> 7;
    const int ntiles = (M >> 7) * nx;
    const int NC = K / GK;

    const int a_r = lane & 15;
    const int a_h = lane >> 4;
    const int b_g = lane >> 3;
    const int b_r = lane & 7;
    const int b_jj = b_g >> 1;
    const int b_h = b_g & 1;

    for (int t = blockIdx.x; t < ntiles; t += NPERS) {
        const int bm = (t / nx) << 7;
        const int bn = (t % nx) << 7;
        const __half* srcA = Ah + (size_t)bm * K;
        const __half* srcB = Bh + (size_t)bn * K;

        float acc[4][4][4];
#pragma unroll
        for (int i = 0; i < 4; i++)
#pragma unroll
            for (int j = 0; j < 4; j++)
#pragma unroll
                for (int r = 0; r < 4; r++) acc[i][j][r] = 0.f;

        auto prefetch = [&](int k0, int s) {
            const uint32_t base = sb + s * G1STAGE;
#pragma unroll
            for (int i = 0; i < 4; i++) {
                const int f = tid + i * 256;        // 0..1023
                const int r = f >> 3, sg = f & 7;
                cpa16(base + gsw(r, sg), srcA + (size_t)r * K + k0 + sg * 8);
                cpa16(base + GTILE + gsw(r, sg), srcB + (size_t)r * K + k0 + sg * 8);
            }
            CP_COMMIT();
        };

        __syncthreads();    // previous tile's compute done before buffer reuse
        prefetch(0, 0);
        prefetch(GK, 1);

        for (int c = 0; c < NC; c++) {
            if (c + 1 < NC) { CP_WAIT1(); } else { CP_WAIT0(); }
            __syncthreads();
            if (c + 2 < NC) prefetch((c + 2) * GK, (c + 2) % 3);

            const uint32_t base = sb + (c % 3) * G1STAGE;
#pragma unroll
            for (int ks = 0; ks < 4; ks++) {
                uint32_t ah[4][4];
#pragma unroll
                for (int mt = 0; mt < 4; mt++) {
                    const int row = warp_m * 64 + mt * 16 + a_r;
                    const uint32_t off = gsw(row, ks * 2 + a_h);
                    ldsm_x4(ah[mt][0], ah[mt][1], ah[mt][2], ah[mt][3], base + off);
                }
#pragma unroll
                for (int jp = 0; jp < 2; jp++) {
                    const int rowb = warp_n * 32 + (jp * 2 + b_jj) * 8 + b_r;
                    const uint32_t boff = gsw(rowb, ks * 2 + b_h);
                    uint32_t bh0, bh1, bh2, bh3;
                    ldsm_x4(bh0, bh1, bh2, bh3, base + GTILE + boff);
#pragma unroll
                    for (int mt = 0; mt < 4; mt++) {
                        mma_fp16(acc[mt][jp * 2],     ah[mt][0], ah[mt][1], ah[mt][2], ah[mt][3], bh0, bh1);
                        mma_fp16(acc[mt][jp * 2 + 1], ah[mt][0], ah[mt][1], ah[mt][2], ah[mt][3], bh2, bh3);
                    }
                }
            }
        }

#pragma unroll
        for (int mt = 0; mt < 4; mt++) {
            const int row = bm + warp_m * 64 + mt * 16 + (lane >> 2);
#pragma unroll
            for (int nt = 0; nt < 4; nt++) {
                const int col = bn + warp_n * 32 + nt * 8 + (lane & 3) * 2;
                float* cp0 = C + (size_t)row * N + col;
                float* cp1 = C + (size_t)(row + 8) * N + col;
                *(float2*)cp0 = make_float2(acc[mt][nt][0], acc[mt][nt][1]);
                *(float2*)cp1 = make_float2(acc[mt][nt][2], acc[mt][nt][3]);
            }
        }
    }
}

// ---------------------------------------------------------------------------
// RMSNorm + RoPE, warp-per-head (R11 verified, unchanged).
// ---------------------------------------------------------------------------
__global__ void __launch_bounds__(256) norm_rope_split_kernel(
    const float* __restrict__ qkv,
    const float* __restrict__ qw, const float* __restrict__ kw,
    __half* __restrict__ qh, __half* __restrict__ ql,
    __half* __restrict__ kk, __half* __restrict__ vv)
{
    const int token = blockIdx.x;
    const int b = token / SEQ;
    const int s = token - b * SEQ;
    const int warp = threadIdx.x >> 5;
    const int lane = threadIdx.x & 31;
    const int head = blockIdx.y * 8 + warp;      // 0..47
    const int d0 = lane * 4;

    if (head >= NH + NKV) {                      // V: convert only
        const int kvh = head - NH - NKV;
        const float4 x = *(const float4*)(qkv + (size_t)token * QKVO
                          + (size_t)(NH + NKV) * HD + (size_t)kvh * HD + d0);
        __half h[4] = { __float2half_rn(x.x), __float2half_rn(x.y),
                        __float2half_rn(x.z), __float2half_rn(x.w) };
        *(uint2*)(vv + ((size_t)(b * NKV + kvh) * SEQ + s) * HD + d0) = *(uint2*)h;
        return;
    }

    const bool is_q = head < NH;
    const float* src = qkv + (size_t)token * QKVO
                     + (is_q ? (size_t)head * HD : (size_t)NH * HD + (size_t)(head - NH) * HD);
    const float4 x = *(const float4*)(src + d0);

    float sq = x.x * x.x + x.y * x.y + x.z * x.z + x.w * x.w;
#pragma unroll
    for (int o = 16; o > 0; o >>= 1) sq += __shfl_xor_sync(0xffffffffu, sq, o);
    const float rn = rsqrtf(sq * (1.0f / HD) + 1e-6f);

    const float4 w = *(const float4*)((is_q ? qw : kw) + d0);
    float y[4] = { x.x * rn * w.x, x.y * rn * w.y, x.z * rn * w.z, x.w * rn * w.w };
    float p[4];
#pragma unroll
    for (int j = 0; j < 4; j++) p[j] = __shfl_xor_sync(0xffffffffu, y[j], 16);

    const int i0 = d0 & 63;
    float outv[4];
#pragma unroll
    for (int j = 0; j < 4; j++) {
        const float2 cs = g_rope[(size_t)s * 64 + i0 + j];
        outv[j] = (lane < 16) ? (y[j] * cs.x - p[j] * cs.y)
                              : (y[j] * cs.x + p[j] * cs.y);
    }

    if (is_q) {
        const size_t o = ((size_t)(b * NH + head) * SEQ + s) * HD + d0;
        __half h[4], l[4];
#pragma unroll
        for (int j = 0; j < 4; j++) {
            const float v = outv[j] * 0.08838834764831843f;
            h[j] = __float2half_rn(v);
            l[j] = __float2half_rn(v - __half2float(h[j]));
        }
        *(uint2*)(qh + o) = *(uint2*)h;
        *(uint2*)(ql + o) = *(uint2*)l;
    } else {
        const size_t o = ((size_t)(b * NKV + (head - NH)) * SEQ + s) * HD + d0;
        __half h[4] = { __float2half_rn(outv[0]), __float2half_rn(outv[1]),
                        __float2half_rn(outv[2]), __float2half_rn(outv[3]) };
        *(uint2*)(kk + o) = *(uint2*)h;
    }
}

// ---------------------------------------------------------------------------
// Tensor-core causal flash attention, fp16x2, BQ=64 (R12 verified version).
// Single fp16 output.
// ---------------------------------------------------------------------------
#define DS 136
#define FTB (64 * DS * 2)
#define FL_SMEM (2 * FTB)

__global__ void __launch_bounds__(128) flash_mma_kernel(
    const __half* __restrict__ gqh, const __half* __restrict__ gql,
    const __half* __restrict__ gkk, const __half* __restrict__ gvv,
    __half* __restrict__ outh)
{
    extern __shared__ char smem[];
    const uint32_t sb = smem_to_u32(smem);
    const uint32_t sK = sb, sV = sb + FTB;

    const int qt = blockIdx.x;
    const int h  = blockIdx.y;
    const int b  = blockIdx.z;
    const int kvh = h >> 2;
    const int tid = threadIdx.x;
    const int wid = tid >> 5;
    const int lane = tid & 31;
    const int m0 = wid * 16;

    const __half* Qh = gqh + ((size_t)(b * NH + h) * SEQ + (size_t)qt * 64) * HD;
    const __half* Ql = gql + ((size_t)(b * NH + h) * SEQ + (size_t)qt * 64) * HD;
    const __half* K  = gkk + (size_t)(b * NKV + kvh) * SEQ * HD;
    const __half* V  = gvv + (size_t)(b * NKV + kvh) * SEQ * HD;

    auto loadtile = [&](uint32_t dst, const __half* src) {
#pragma unroll
        for (int i = 0; i < 8; i++) {
            const int f = tid + i * 128;
            const int r = f >> 4, sg = f & 15;
            cpa16(dst + (uint32_t)(r * DS + sg * 8) * 2, src + (size_t)r * HD + sg * 8);
        }
    };

    const int a_r = lane & 15, a_c = (lane >> 4) * 8;
    const int b_r = lane & 7,  b_g = lane >> 3;
    const int b_jj = b_g >> 1, b_kk = (b_g & 1) * 8;
    const int qrow = lane >> 2;
    const int qcol = (lane & 3) * 2;

    loadtile(sK, Qh);
    loadtile(sV, Ql);
    CP_COMMIT();
    CP_WAIT0();
    __syncthreads();
    uint32_t qfh[8][4], qfl[8][4];
#pragma unroll
    for (int kb = 0; kb < 8; kb++) {
        const uint32_t aoff = (uint32_t)((m0 + a_r) * DS + kb * 16 + a_c) * 2;
        ldsm_x4(qfh[kb][0], qfh[kb][1], qfh[kb][2], qfh[kb][3], sK + aoff);
        ldsm_x4(qfl[kb][0], qfl[kb][1], qfl[kb][2], qfl[kb][3], sV + aoff);
    }
    __syncthreads();

    float o[16][4];
#pragma unroll
    for (int i = 0; i < 16; i++)
#pragma unroll
        for (int j = 0; j < 4; j++) o[i][j] = 0.f;
    float mrow[2] = {-INFINITY, -INFINITY};
    float lrow[2] = {0.f, 0.f};

    for (int jt = 0; jt <= qt; jt++) {
        loadtile(sK, K + (size_t)jt * 64 * HD);
        loadtile(sV, V + (size_t)jt * 64 * HD);
        CP_COMMIT();
        CP_WAIT0();
        __syncthreads();

        float sc[8][4];
#pragma unroll
        for (int i = 0; i < 8; i++)
#pragma unroll
            for (int j = 0; j < 4; j++) sc[i][j] = 0.f;

#pragma unroll
        for (int kb = 0; kb < 8; kb++) {
#pragma unroll
            for (int np = 0; np < 4; np++) {
                const uint32_t boff =
                    (uint32_t)(((np * 2 + b_jj) * 8 + b_r) * DS + kb * 16 + b_kk) * 2;
                uint32_t k0, k1, k2, k3;
                ldsm_x4(k0, k1, k2, k3, sK + boff);
                float* c0 = sc[np * 2];
                float* c1 = sc[np * 2 + 1];
                mma_fp16(c0, qfh[kb][0], qfh[kb][1], qfh[kb][2], qfh[kb][3], k0, k1);
                mma_fp16(c1, qfh[kb][0], qfh[kb][1], qfh[kb][2], qfh[kb][3], k2, k3);
                mma_fp16(c0, qfl[kb][0], qfl[kb][1], qfl[kb][2], qfl[kb][3], k0, k1);
                mma_fp16(c1, qfl[kb][0], qfl[kb][1], qfl[kb][2], qfl[kb][3], k2, k3);
            }
        }

        if (jt == qt) {
            const int r0 = m0 + qrow, r1 = r0 + 8;
#pragma unroll
            for (int nt = 0; nt < 8; nt++) {
                const int col = nt * 8 + qcol;
                if (col > r0)     sc[nt][0] = -INFINITY;
                if (col + 1 > r0) sc[nt][1] = -INFINITY;
                if (col > r1)     sc[nt][2] = -INFINITY;
                if (col + 1 > r1) sc[nt][3] = -INFINITY;
            }
        }

        float mx0 = -INFINITY, mx1 = -INFINITY;
#pragma unroll
        for (int nt = 0; nt < 8; nt++) {
            mx0 = fmaxf(mx0, fmaxf(sc[nt][0], sc[nt][1]));
            mx1 = fmaxf(mx1, fmaxf(sc[nt][2], sc[nt][3]));
        }
        mx0 = fmaxf(mx0, __shfl_xor_sync(0xffffffffu, mx0, 1));
        mx0 = fmaxf(mx0, __shfl_xor_sync(0xffffffffu, mx0, 2));
        mx1 = fmaxf(mx1, __shfl_xor_sync(0xffffffffu, mx1, 1));
        mx1 = fmaxf(mx1, __shfl_xor_sync(0xffffffffu, mx1, 2));
        const float mn0 = fmaxf(mrow[0], mx0);
        const float mn1 = fmaxf(mrow[1], mx1);
        const float cr0 = __expf(mrow[0] - mn0);
        const float cr1 = __expf(mrow[1] - mn1);
        mrow[0] = mn0; mrow[1] = mn1;

        float s0 = 0.f, s1 = 0.f;
#pragma unroll
        for (int nt = 0; nt < 8; nt++) {
            sc[nt][0] = __expf(sc[nt][0] - mn0); s0 += sc[nt][0];
            sc[nt][1] = __expf(sc[nt][1] - mn0); s0 += sc[nt][1];
            sc[nt][2] = __expf(sc[nt][2] - mn1); s1 += sc[nt][2];
            sc[nt][3] = __expf(sc[nt][3] - mn1); s1 += sc[nt][3];
        }
        s0 += __shfl_xor_sync(0xffffffffu, s0, 1);
        s0 += __shfl_xor_sync(0xffffffffu, s0, 2);
        s1 += __shfl_xor_sync(0xffffffffu, s1, 1);
        s1 += __shfl_xor_sync(0xffffffffu, s1, 2);
        lrow[0] = lrow[0] * cr0 + s0;
        lrow[1] = lrow[1] * cr1 + s1;

#pragma unroll
        for (int nt = 0; nt < 16; nt++) {
            o[nt][0] *= cr0; o[nt][1] *= cr0;
            o[nt][2] *= cr1; o[nt][3] *= cr1;
        }

#pragma unroll
        for (int kc = 0; kc < 4; kc++) {
            const float p00 = sc[kc * 2][0],     p01 = sc[kc * 2][1];
            const float p10 = sc[kc * 2][2],     p11 = sc[kc * 2][3];
            const float p20 = sc[kc * 2 + 1][0], p21 = sc[kc * 2 + 1][1];
            const float p30 = sc[kc * 2 + 1][2], p31 = sc[kc * 2 + 1][3];
            const uint32_t ph0 = pack2_fp16(p00, p01);
            const uint32_t ph1 = pack2_fp16(p10, p11);
            const uint32_t ph2 = pack2_fp16(p20, p21);
            const uint32_t ph3 = pack2_fp16(p30, p31);
            float2 f0 = __half22float2(*(__half2*)&ph0);
            float2 f1 = __half22float2(*(__half2*)&ph1);
            float2 f2 = __half22float2(*(__half2*)&ph2);
            float2 f3 = __half22float2(*(__half2*)&ph3);
            const uint32_t pl0 = pack2_fp16(p00 - f0.x, p01 - f0.y);
            const uint32_t pl1 = pack2_fp16(p10 - f1.x, p11 - f1.y);
            const uint32_t pl2 = pack2_fp16(p20 - f2.x, p21 - f2.y);
            const uint32_t pl3 = pack2_fp16(p30 - f3.x, p31 - f3.y);

#pragma unroll
            for (int npair = 0; npair < 8; npair++) {
                const uint32_t voff =
                    (uint32_t)((kc * 16 + a_r) * DS + npair * 16 + a_c) * 2;
                uint32_t v0, v1, v2, v3;
                ldsm_x4_t(v0, v1, v2, v3, sV + voff);
                float* c0 = o[npair * 2];
                float* c1 = o[npair * 2 + 1];
                mma_fp16(c0, ph0, ph1, ph2, ph3, v0, v1);
                mma_fp16(c1, ph0, ph1, ph2, ph3, v2, v3);
                mma_fp16(c0, pl0, pl1, pl2, pl3, v0, v1);
                mma_fp16(c1, pl0, pl1, pl2, pl3, v2, v3);
            }
        }
        __syncthreads();
    }

    const float iv0 = 1.f / lrow[0];
    const float iv1 = 1.f / lrow[1];
    const size_t t0 = (size_t)b * SEQ + (size_t)qt * 64 + m0 + qrow;
    const size_t t1 = t0 + 8;
#pragma unroll
    for (int nt = 0; nt < 16; nt++) {
        const int col = h * HD + nt * 8 + qcol;
        *(__half2*)(outh + t0 * HID + col) =
            __floats2half2_rn(o[nt][0] * iv0, o[nt][1] * iv0);
        *(__half2*)(outh + t1 * HID + col) =
            __floats2half2_rn(o[nt][2] * iv1, o[nt][3] * iv1);
    }
}

// ---------------------------------------------------------------------------
extern "C" void kernel_launch(void* const* d_in, const int* in_sizes, int n_in,
                              void* d_out, int out_size)
{
    const float* hidden    = (const float*)d_in[0];
    const int*   positions = (const int*)d_in[1];
    const float* wqkv      = (const float*)d_in[2];
    const float* qnw       = (const float*)d_in[3];
    const float* knw       = (const float*)d_in[4];
    const float* wo        = (const float*)d_in[5];
    float* out = (float*)d_out;

    float* qkv;
    __half *ah, *wh, *qh, *ql, *kk, *vv;
    cudaGetSymbolAddress((void**)&qkv, g_qkv);
    cudaGetSymbolAddress((void**)&ah, g_ah);
    cudaGetSymbolAddress((void**)&wh, g_wh);
    cudaGetSymbolAddress((void**)&qh, g_qhh);
    cudaGetSymbolAddress((void**)&ql, g_qll);
    cudaGetSymbolAddress((void**)&kk, g_kk);
    cudaGetSymbolAddress((void**)&vv, g_vv);

    cudaFuncSetAttribute(gemm_fp16x1_kernel,
                         cudaFuncAttributeMaxDynamicSharedMemorySize, GEMM1_SMEM);
    cudaFuncSetAttribute(flash_mma_kernel,
                         cudaFuncAttributeMaxDynamicSharedMemorySize, FL_SMEM);

    const size_t nA  = (size_t)MTOK * HID;
    const size_t nW1 = (size_t)QKVO * HID;

    // 0) RoPE table
    rope_table_kernel<<<(SEQ * 64 + 255) / 256, 256>>>(positions);

    // 1) convert hidden and wqkv to fp16
    conv_fp16_kernel<<<(unsigned)((nA / 4 + 255) / 256), 256>>>(hidden, ah, nA);
    conv_fp16_kernel<<<(unsigned)((nW1 / 4 + 255) / 256), 256>>>(wqkv, wh, nW1);

    // 2) QKV projection (persistent fp16x1)
    gemm_fp16x1_kernel<<<NPERS, 256, GEMM1_SMEM>>>(ah, wh, qkv, MTOK, QKVO, HID);

    // 3) RMSNorm + RoPE, warp-per-head
    dim3 g2(MTOK, 6);
    norm_rope_split_kernel<<<g2, 256>>>(qkv, qnw, knw, qh, ql, kk, vv);

    // 4) Flash attention (fp16x2, BQ=64) -> single fp16 attn (reuse ah)
    dim3 g3(SEQ / 64, NH, NB);
    flash_mma_kernel<<<g3, 128, FL_SMEM>>>(qh, ql, kk, vv, ah);

    // 5) convert wo, output projection (persistent fp16x1)
    conv_fp16_kernel<<<(unsigned)((nA / 4 + 255) / 256), 256>>>(wo, wh, nA);
    gemm_fp16x1_kernel<<<NPERS, 256, GEMM1_SMEM>>>(ah, wh, out, MTOK, HID, HID);
}

// round 16
// speedup vs baseline: 1.0370x; 1.0370x over previous
#include <cuda_runtime.h>
#include <cuda_fp16.h>
#include <math.h>
#include <stdint.h>

// Problem constants
#define NB   2
#define SEQ  2048
#define HID  4096
#define NH   32
#define NKV  8
#define HD   128
#define QKVO ((NH + 2*NKV)*HD)   // 6144
#define MTOK (NB*SEQ)            // 4096

// Scratch
__device__ float g_qkv[(size_t)MTOK * QKVO];
__device__ __half g_ah[(size_t)MTOK * HID];
__device__ __half g_wh[(size_t)QKVO * HID];
__device__ __half g_who[(size_t)HID * HID];
__device__ __half g_qhh[(size_t)NB * NH * SEQ * HD];
__device__ __half g_qll[(size_t)NB * NH * SEQ * HD];
__device__ __half g_kk[(size_t)NB * NKV * SEQ * HD];
__device__ __half g_vv[(size_t)NB * NKV * SEQ * HD];
__device__ float2 g_rope[(size_t)SEQ * 64];

// ===========================================================================
// Low-level helpers
// ===========================================================================
__device__ __forceinline__ uint32_t smem_to_u32(const void* p) {
    uint32_t a;
    asm("{ .reg .u64 t; cvta.to.shared.u64 t, %1; cvt.u32.u64 %0, t; }" : "=r"(a) : "l"(p));
    return a;
}
__device__ __forceinline__ void ldsm_x4(uint32_t& r0, uint32_t& r1, uint32_t& r2,
                                        uint32_t& r3, uint32_t addr) {
    asm volatile("ldmatrix.sync.aligned.m8n8.x4.shared.b16 {%0,%1,%2,%3}, [%4];"
                 : "=r"(r0), "=r"(r1), "=r"(r2), "=r"(r3) : "r"(addr));
}
__device__ __forceinline__ void ldsm_x4_t(uint32_t& r0, uint32_t& r1, uint32_t& r2,
                                          uint32_t& r3, uint32_t addr) {
    asm volatile("ldmatrix.sync.aligned.m8n8.x4.trans.shared.b16 {%0,%1,%2,%3}, [%4];"
                 : "=r"(r0), "=r"(r1), "=r"(r2), "=r"(r3) : "r"(addr));
}
__device__ __forceinline__ void mma_fp16(float* c, uint32_t a0, uint32_t a1,
                                         uint32_t a2, uint32_t a3,
                                         uint32_t b0, uint32_t b1) {
    asm volatile(
        "mma.sync.aligned.m16n8k16.row.col.f32.f16.f16.f32 "
        "{%0,%1,%2,%3}, {%4,%5,%6,%7}, {%8,%9}, {%0,%1,%2,%3};"
        : "+f"(c[0]), "+f"(c[1]), "+f"(c[2]), "+f"(c[3])
        : "r"(a0), "r"(a1), "r"(a2), "r"(a3), "r"(b0), "r"(b1));
}
__device__ __forceinline__ void cpa16(uint32_t dst, const void* src) {
    asm volatile("cp.async.cg.shared.global [%0], [%1], 16;" :: "r"(dst), "l"(src));
}
#define CP_COMMIT() asm volatile("cp.async.commit_group;" ::: "memory")
#define CP_WAIT0()  asm volatile("cp.async.wait_group 0;" ::: "memory")
#define CP_WAIT1()  asm volatile("cp.async.wait_group 1;" ::: "memory")

__device__ __forceinline__ uint32_t pack2_fp16(float a, float b) {
    __half2 t = __floats2half2_rn(a, b);
    return *reinterpret_cast<uint32_t*>(&t);
}

// ===========================================================================
// RoPE table (fp64 once)
// ===========================================================================
__global__ void __launch_bounds__(256) rope_table_kernel(const int* __restrict__ positions)
{
    const int idx = blockIdx.x * 256 + threadIdx.x;
    if (idx >= SEQ * 64) return;
    const int s = idx >> 6, i = idx & 63;
    const int pos = positions[s];
    const double inv = exp(-(double)i * (9.210340371976184 / 64.0));
    double sd, cd;
    sincos((double)pos * inv, &sd, &cd);
    g_rope[idx] = make_float2((float)cd, (float)sd);
}

// ===========================================================================
// Merged conversion: hidden->ah, wqkv->wh, wo->who in one launch.
// ===========================================================================
#define N_A ((size_t)MTOK * HID)
#define N_W1 ((size_t)QKVO * HID)
#define CV1 (N_A / 4)
#define CV2 (CV1 + N_W1 / 4)
#define CVTOT (CV2 + N_A / 4)

__global__ void __launch_bounds__(256) conv_all_kernel(
    const float* __restrict__ hidden, const float* __restrict__ wqkv,
    const float* __restrict__ wo,
    __half* __restrict__ ah, __half* __restrict__ wh, __half* __restrict__ who)
{
    const size_t i = (size_t)blockIdx.x * 256 + threadIdx.x;
    if (i >= CVTOT) return;
    const float* src;
    __half* dst;
    size_t off;
    if (i < CV1)      { src = hidden; dst = ah;  off = i; }
    else if (i < CV2) { src = wqkv;   dst = wh;  off = i - CV1; }
    else              { src = wo;     dst = who; off = i - CV2; }
    float4 v = *(const float4*)(src + off * 4);
    __half h[4] = { __float2half_rn(v.x), __float2half_rn(v.y),
                    __float2half_rn(v.z), __float2half_rn(v.w) };
    *(uint2*)(dst + off * 4) = *(uint2*)h;
}

// ===========================================================================
// Shared GEMM geometry: 128B-row XOR-swizzled tiles
// ===========================================================================
#define GK 64
#define GTILE 16384                  // 128 rows * 128 B

__device__ __forceinline__ uint32_t gsw(int row, int seg) {
    return (uint32_t)(row * 128 + ((seg ^ row) & 7) * 16);
}

// ===========================================================================
// fp16x1 GEMM-NT (R12 verified): 3-stage, 2 CTAs/SM.
// ===========================================================================
#define G1STAGE (2 * GTILE)          // Ah, Bh = 32768 B
#define GEMM1_SMEM (3 * G1STAGE)     // 98304 B

__global__ void __launch_bounds__(256, 2) gemm_fp16x1_kernel(
    const __half* __restrict__ Ah, const __half* __restrict__ Bh,
    float* __restrict__ C, int M, int N, int K)
{
    extern __shared__ char smem[];
    const uint32_t sb = smem_to_u32(smem);
    const int tid  = threadIdx.x;
    const int wid  = tid >> 5;
    const int lane = tid & 31;
    const int warp_m = wid >> 2;
    const int warp_n = wid & 3;
    const int bm = blockIdx.y * 128;
    const int bn = blockIdx.x * 128;

    const __half* srcs[2] = { Ah + (size_t)bm * K, Bh + (size_t)bn * K };

    float acc[4][4][4];
#pragma unroll
    for (int i = 0; i < 4; i++)
#pragma unroll
        for (int j = 0; j < 4; j++)
#pragma unroll
            for (int r = 0; r < 4; r++) acc[i][j][r] = 0.f;

    auto prefetch = [&](int k0, int s) {
        const uint32_t base = sb + s * G1STAGE;
#pragma unroll
        for (int t = 0; t < 2; t++) {
            const __half* src = srcs[t];
            const uint32_t tb = base + t * GTILE;
#pragma unroll
            for (int i = 0; i < 4; i++) {
                const int f = tid + i * 256;        // 0..1023
                const int r = f >> 3, sg = f & 7;
                cpa16(tb + gsw(r, sg), src + (size_t)r * K + k0 + sg * 8);
            }
        }
        CP_COMMIT();
    };

    const int NC = K / GK;
    prefetch(0, 0);
    prefetch(GK, 1);

    const int a_r = lane & 15;
    const int a_h = lane >> 4;
    const int b_g = lane >> 3;
    const int b_r = lane & 7;
    const int b_jj = b_g >> 1;
    const int b_h = b_g & 1;

    for (int c = 0; c < NC; c++) {
        if (c + 1 < NC) { CP_WAIT1(); } else { CP_WAIT0(); }
        __syncthreads();
        if (c + 2 < NC) prefetch((c + 2) * GK, (c + 2) % 3);

        const uint32_t base = sb + (c % 3) * G1STAGE;
#pragma unroll
        for (int ks = 0; ks < 4; ks++) {
            uint32_t ah[4][4];
#pragma unroll
            for (int mt = 0; mt < 4; mt++) {
                const int row = warp_m * 64 + mt * 16 + a_r;
                const uint32_t off = gsw(row, ks * 2 + a_h);
                ldsm_x4(ah[mt][0], ah[mt][1], ah[mt][2], ah[mt][3], base + off);
            }
#pragma unroll
            for (int jp = 0; jp < 2; jp++) {
                const int rowb = warp_n * 32 + (jp * 2 + b_jj) * 8 + b_r;
                const uint32_t boff = gsw(rowb, ks * 2 + b_h);
                uint32_t bh0, bh1, bh2, bh3;
                ldsm_x4(bh0, bh1, bh2, bh3, base + GTILE + boff);
#pragma unroll
                for (int mt = 0; mt < 4; mt++) {
                    mma_fp16(acc[mt][jp * 2],     ah[mt][0], ah[mt][1], ah[mt][2], ah[mt][3], bh0, bh1);
                    mma_fp16(acc[mt][jp * 2 + 1], ah[mt][0], ah[mt][1], ah[mt][2], ah[mt][3], bh2, bh3);
                }
            }
        }
    }

#pragma unroll
    for (int mt = 0; mt < 4; mt++) {
        const int row = bm + warp_m * 64 + mt * 16 + (lane >> 2);
#pragma unroll
        for (int nt = 0; nt < 4; nt++) {
            const int col = bn + warp_n * 32 + nt * 8 + (lane & 3) * 2;
            float* cp0 = C + (size_t)row * N + col;
            float* cp1 = C + (size_t)(row + 8) * N + col;
            *(float2*)cp0 = make_float2(acc[mt][nt][0], acc[mt][nt][1]);
            *(float2*)cp1 = make_float2(acc[mt][nt][2], acc[mt][nt][3]);
        }
    }
}

// ---------------------------------------------------------------------------
// RMSNorm + RoPE, warp-per-head (R11 verified, unchanged).
// ---------------------------------------------------------------------------
__global__ void __launch_bounds__(256) norm_rope_split_kernel(
    const float* __restrict__ qkv,
    const float* __restrict__ qw, const float* __restrict__ kw,
    __half* __restrict__ qh, __half* __restrict__ ql,
    __half* __restrict__ kk, __half* __restrict__ vv)
{
    const int token = blockIdx.x;
    const int b = token / SEQ;
    const int s = token - b * SEQ;
    const int warp = threadIdx.x >> 5;
    const int lane = threadIdx.x & 31;
    const int head = blockIdx.y * 8 + warp;      // 0..47
    const int d0 = lane * 4;

    if (head >= NH + NKV) {                      // V: convert only
        const int kvh = head - NH - NKV;
        const float4 x = *(const float4*)(qkv + (size_t)token * QKVO
                          + (size_t)(NH + NKV) * HD + (size_t)kvh * HD + d0);
        __half h[4] = { __float2half_rn(x.x), __float2half_rn(x.y),
                        __float2half_rn(x.z), __float2half_rn(x.w) };
        *(uint2*)(vv + ((size_t)(b * NKV + kvh) * SEQ + s) * HD + d0) = *(uint2*)h;
        return;
    }

    const bool is_q = head < NH;
    const float* src = qkv + (size_t)token * QKVO
                     + (is_q ? (size_t)head * HD : (size_t)NH * HD + (size_t)(head - NH) * HD);
    const float4 x = *(const float4*)(src + d0);

    float sq = x.x * x.x + x.y * x.y + x.z * x.z + x.w * x.w;
#pragma unroll
    for (int o = 16; o > 0; o >>= 1) sq += __shfl_xor_sync(0xffffffffu, sq, o);
    const float rn = rsqrtf(sq * (1.0f / HD) + 1e-6f);

    const float4 w = *(const float4*)((is_q ? qw : kw) + d0);
    float y[4] = { x.x * rn * w.x, x.y * rn * w.y, x.z * rn * w.z, x.w * rn * w.w };
    float p[4];
#pragma unroll
    for (int j = 0; j < 4; j++) p[j] = __shfl_xor_sync(0xffffffffu, y[j], 16);

    const int i0 = d0 & 63;
    float outv[4];
#pragma unroll
    for (int j = 0; j < 4; j++) {
        const float2 cs = g_rope[(size_t)s * 64 + i0 + j];
        outv[j] = (lane < 16) ? (y[j] * cs.x - p[j] * cs.y)
                              : (y[j] * cs.x + p[j] * cs.y);
    }

    if (is_q) {
        const size_t o = ((size_t)(b * NH + head) * SEQ + s) * HD + d0;
        __half h[4], l[4];
#pragma unroll
        for (int j = 0; j < 4; j++) {
            const float v = outv[j] * 0.08838834764831843f;
            h[j] = __float2half_rn(v);
            l[j] = __float2half_rn(v - __half2float(h[j]));
        }
        *(uint2*)(qh + o) = *(uint2*)h;
        *(uint2*)(ql + o) = *(uint2*)l;
    } else {
        const size_t o = ((size_t)(b * NKV + (head - NH)) * SEQ + s) * HD + d0;
        __half h[4] = { __float2half_rn(outv[0]), __float2half_rn(outv[1]),
                        __float2half_rn(outv[2]), __float2half_rn(outv[3]) };
        *(uint2*)(kk + o) = *(uint2*)h;
    }
}

// ---------------------------------------------------------------------------
// Tensor-core causal flash attention, fp16x2, BQ=64, 128 threads (R12 regs),
// K/V double-buffered. Single fp16 output.
// ---------------------------------------------------------------------------
#define DS 136
#define FTB (64 * DS * 2)            // 17408
#define FL_SMEM (4 * FTB)            // 69632

__global__ void __launch_bounds__(128) flash_mma_kernel(
    const __half* __restrict__ gqh, const __half* __restrict__ gql,
    const __half* __restrict__ gkk, const __half* __restrict__ gvv,
    __half* __restrict__ outh)
{
    extern __shared__ char smem[];
    const uint32_t sb = smem_to_u32(smem);

    const int qt = blockIdx.x;
    const int h  = blockIdx.y;
    const int b  = blockIdx.z;
    const int kvh = h >> 2;
    const int tid = threadIdx.x;
    const int wid = tid >> 5;
    const int lane = tid & 31;
    const int m0 = wid * 16;

    const __half* Qh = gqh + ((size_t)(b * NH + h) * SEQ + (size_t)qt * 64) * HD;
    const __half* Ql = gql + ((size_t)(b * NH + h) * SEQ + (size_t)qt * 64) * HD;
    const __half* K  = gkk + (size_t)(b * NKV + kvh) * SEQ * HD;
    const __half* V  = gvv + (size_t)(b * NKV + kvh) * SEQ * HD;

    auto loadtile = [&](uint32_t dst, const __half* src) {
#pragma unroll
        for (int i = 0; i < 8; i++) {
            const int f = tid + i * 128;
            const int r = f >> 4, sg = f & 15;
            cpa16(dst + (uint32_t)(r * DS + sg * 8) * 2, src + (size_t)r * HD + sg * 8);
        }
    };

    const int a_r = lane & 15, a_c = (lane >> 4) * 8;
    const int b_r = lane & 7,  b_g = lane >> 3;
    const int b_jj = b_g >> 1, b_kk = (b_g & 1) * 8;
    const int qrow = lane >> 2;
    const int qcol = (lane & 3) * 2;

    // ---- stage Q through ping/pong K buffers, hoist fragments ----
    loadtile(sb, Qh);
    loadtile(sb + 2 * FTB, Ql);
    CP_COMMIT();
    CP_WAIT0();
    __syncthreads();
    uint32_t qfh[8][4], qfl[8][4];
#pragma unroll
    for (int kb = 0; kb < 8; kb++) {
        const uint32_t aoff = (uint32_t)((m0 + a_r) * DS + kb * 16 + a_c) * 2;
        ldsm_x4(qfh[kb][0], qfh[kb][1], qfh[kb][2], qfh[kb][3], sb + aoff);
        ldsm_x4(qfl[kb][0], qfl[kb][1], qfl[kb][2], qfl[kb][3], sb + 2 * FTB + aoff);
    }
    __syncthreads();

    float o[16][4];
#pragma unroll
    for (int i = 0; i < 16; i++)
#pragma unroll
        for (int j = 0; j < 4; j++) o[i][j] = 0.f;
    float mrow[2] = {-INFINITY, -INFINITY};
    float lrow[2] = {0.f, 0.f};

    // prefetch KV tile 0 into ping
    loadtile(sb,       K);
    loadtile(sb + FTB, V);
    CP_COMMIT();

    for (int jt = 0; jt <= qt; jt++) {
        if (jt < qt) {
            const uint32_t nb = sb + ((jt + 1) & 1) * 2 * FTB;
            loadtile(nb,       K + (size_t)(jt + 1) * 64 * HD);
            loadtile(nb + FTB, V + (size_t)(jt + 1) * 64 * HD);
            CP_COMMIT();
            CP_WAIT1();
        } else {
            CP_WAIT0();
        }
        __syncthreads();

        const uint32_t sK = sb + (jt & 1) * 2 * FTB;
        const uint32_t sV = sK + FTB;

        float sc[8][4];
#pragma unroll
        for (int i = 0; i < 8; i++)
#pragma unroll
            for (int j = 0; j < 4; j++) sc[i][j] = 0.f;

#pragma unroll
        for (int kb = 0; kb < 8; kb++) {
#pragma unroll
            for (int np = 0; np < 4; np++) {
                const uint32_t boff =
                    (uint32_t)(((np * 2 + b_jj) * 8 + b_r) * DS + kb * 16 + b_kk) * 2;
                uint32_t k0, k1, k2, k3;
                ldsm_x4(k0, k1, k2, k3, sK + boff);
                float* c0 = sc[np * 2];
                float* c1 = sc[np * 2 + 1];
                mma_fp16(c0, qfh[kb][0], qfh[kb][1], qfh[kb][2], qfh[kb][3], k0, k1);
                mma_fp16(c1, qfh[kb][0], qfh[kb][1], qfh[kb][2], qfh[kb][3], k2, k3);
                mma_fp16(c0, qfl[kb][0], qfl[kb][1], qfl[kb][2], qfl[kb][3], k0, k1);
                mma_fp16(c1, qfl[kb][0], qfl[kb][1], qfl[kb][2], qfl[kb][3], k2, k3);
            }
        }

        if (jt == qt) {
            const int r0 = m0 + qrow, r1 = r0 + 8;
#pragma unroll
            for (int nt = 0; nt < 8; nt++) {
                const int col = nt * 8 + qcol;
                if (col > r0)     sc[nt][0] = -INFINITY;
                if (col + 1 > r0) sc[nt][1] = -INFINITY;
                if (col > r1)     sc[nt][2] = -INFINITY;
                if (col + 1 > r1) sc[nt][3] = -INFINITY;
            }
        }

        float mx0 = -INFINITY, mx1 = -INFINITY;
#pragma unroll
        for (int nt = 0; nt < 8; nt++) {
            mx0 = fmaxf(mx0, fmaxf(sc[nt][0], sc[nt][1]));
            mx1 = fmaxf(mx1, fmaxf(sc[nt][2], sc[nt][3]));
        }
        mx0 = fmaxf(mx0, __shfl_xor_sync(0xffffffffu, mx0, 1));
        mx0 = fmaxf(mx0, __shfl_xor_sync(0xffffffffu, mx0, 2));
        mx1 = fmaxf(mx1, __shfl_xor_sync(0xffffffffu, mx1, 1));
        mx1 = fmaxf(mx1, __shfl_xor_sync(0xffffffffu, mx1, 2));
        const float mn0 = fmaxf(mrow[0], mx0);
        const float mn1 = fmaxf(mrow[1], mx1);
        const float cr0 = __expf(mrow[0] - mn0);
        const float cr1 = __expf(mrow[1] - mn1);
        mrow[0] = mn0; mrow[1] = mn1;

        float s0 = 0.f, s1 = 0.f;
#pragma unroll
        for (int nt = 0; nt < 8; nt++) {
            sc[nt][0] = __expf(sc[nt][0] - mn0); s0 += sc[nt][0];
            sc[nt][1] = __expf(sc[nt][1] - mn0); s0 += sc[nt][1];
            sc[nt][2] = __expf(sc[nt][2] - mn1); s1 += sc[nt][2];
            sc[nt][3] = __expf(sc[nt][3] - mn1); s1 += sc[nt][3];
        }
        s0 += __shfl_xor_sync(0xffffffffu, s0, 1);
        s0 += __shfl_xor_sync(0xffffffffu, s0, 2);
        s1 += __shfl_xor_sync(0xffffffffu, s1, 1);
        s1 += __shfl_xor_sync(0xffffffffu, s1, 2);
        lrow[0] = lrow[0] * cr0 + s0;
        lrow[1] = lrow[1] * cr1 + s1;

#pragma unroll
        for (int nt = 0; nt < 16; nt++) {
            o[nt][0] *= cr0; o[nt][1] *= cr0;
            o[nt][2] *= cr1; o[nt][3] *= cr1;
        }

#pragma unroll
        for (int kc = 0; kc < 4; kc++) {
            const float p00 = sc[kc * 2][0],     p01 = sc[kc * 2][1];
            const float p10 = sc[kc * 2][2],     p11 = sc[kc * 2][3];
            const float p20 = sc[kc * 2 + 1][0], p21 = sc[kc * 2 + 1][1];
            const float p30 = sc[kc * 2 + 1][2], p31 = sc[kc * 2 + 1][3];
            const uint32_t ph0 = pack2_fp16(p00, p01);
            const uint32_t ph1 = pack2_fp16(p10, p11);
            const uint32_t ph2 = pack2_fp16(p20, p21);
            const uint32_t ph3 = pack2_fp16(p30, p31);
            float2 f0 = __half22float2(*(__half2*)&ph0);
            float2 f1 = __half22float2(*(__half2*)&ph1);
            float2 f2 = __half22float2(*(__half2*)&ph2);
            float2 f3 = __half22float2(*(__half2*)&ph3);
            const uint32_t pl0 = pack2_fp16(p00 - f0.x, p01 - f0.y);
            const uint32_t pl1 = pack2_fp16(p10 - f1.x, p11 - f1.y);
            const uint32_t pl2 = pack2_fp16(p20 - f2.x, p21 - f2.y);
            const uint32_t pl3 = pack2_fp16(p30 - f3.x, p31 - f3.y);

#pragma unroll
            for (int npair = 0; npair < 8; npair++) {
                const uint32_t voff =
                    (uint32_t)((kc * 16 + a_r) * DS + npair * 16 + a_c) * 2;
                uint32_t v0, v1, v2, v3;
                ldsm_x4_t(v0, v1, v2, v3, sV + voff);
                float* c0 = o[npair * 2];
                float* c1 = o[npair * 2 + 1];
                mma_fp16(c0, ph0, ph1, ph2, ph3, v0, v1);
                mma_fp16(c1, ph0, ph1, ph2, ph3, v2, v3);
                mma_fp16(c0, pl0, pl1, pl2, pl3, v0, v1);
                mma_fp16(c1, pl0, pl1, pl2, pl3, v2, v3);
            }
        }
        __syncthreads();
    }

    const float iv0 = 1.f / lrow[0];
    const float iv1 = 1.f / lrow[1];
    const size_t t0 = (size_t)b * SEQ + (size_t)qt * 64 + m0 + qrow;
    const size_t t1 = t0 + 8;
#pragma unroll
    for (int nt = 0; nt < 16; nt++) {
        const int col = h * HD + nt * 8 + qcol;
        *(__half2*)(outh + t0 * HID + col) =
            __floats2half2_rn(o[nt][0] * iv0, o[nt][1] * iv0);
        *(__half2*)(outh + t1 * HID + col) =
            __floats2half2_rn(o[nt][2] * iv1, o[nt][3] * iv1);
    }
}

// ---------------------------------------------------------------------------
extern "C" void kernel_launch(void* const* d_in, const int* in_sizes, int n_in,
                              void* d_out, int out_size)
{
    const float* hidden    = (const float*)d_in[0];
    const int*   positions = (const int*)d_in[1];
    const float* wqkv      = (const float*)d_in[2];
    const float* qnw       = (const float*)d_in[3];
    const float* knw       = (const float*)d_in[4];
    const float* wo        = (const float*)d_in[5];
    float* out = (float*)d_out;

    float* qkv;
    __half *ah, *wh, *who, *qh, *ql, *kk, *vv;
    cudaGetSymbolAddress((void**)&qkv, g_qkv);
    cudaGetSymbolAddress((void**)&ah, g_ah);
    cudaGetSymbolAddress((void**)&wh, g_wh);
    cudaGetSymbolAddress((void**)&who, g_who);
    cudaGetSymbolAddress((void**)&qh, g_qhh);
    cudaGetSymbolAddress((void**)&ql, g_qll);
    cudaGetSymbolAddress((void**)&kk, g_kk);
    cudaGetSymbolAddress((void**)&vv, g_vv);

    cudaFuncSetAttribute(gemm_fp16x1_kernel,
                         cudaFuncAttributeMaxDynamicSharedMemorySize, GEMM1_SMEM);
    cudaFuncSetAttribute(flash_mma_kernel,
                         cudaFuncAttributeMaxDynamicSharedMemorySize, FL_SMEM);

    // 0) RoPE table
    rope_table_kernel<<<(SEQ * 64 + 255) / 256, 256>>>(positions);

    // 1) merged conversions: hidden->ah, wqkv->wh, wo->who
    conv_all_kernel<<<(unsigned)((CVTOT + 255) / 256), 256>>>(
        hidden, wqkv, wo, ah, wh, who);

    // 2) QKV projection (fp16x1)
    dim3 g1(QKVO / 128, MTOK / 128);
    gemm_fp16x1_kernel<<<g1, 256, GEMM1_SMEM>>>(ah, wh, qkv, MTOK, QKVO, HID);

    // 3) RMSNorm + RoPE, warp-per-head
    dim3 g2(MTOK, 6);
    norm_rope_split_kernel<<<g2, 256>>>(qkv, qnw, knw, qh, ql, kk, vv);

    // 4) Flash attention (fp16x2, BQ=64, double-buffered K/V) -> fp16 attn
    dim3 g3(SEQ / 64, NH, NB);
    flash_mma_kernel<<<g3, 128, FL_SMEM>>>(qh, ql, kk, vv, ah);

    // 5) output projection (fp16x1)
    dim3 g4(HID / 128, MTOK / 128);
    gemm_fp16x1_kernel<<<g4, 256, GEMM1_SMEM>>>(ah, who, out, MTOK, HID, HID);
}

// round 17
// speedup vs baseline: 1.0817x; 1.0431x over previous
#include <cuda_runtime.h>
#include <cuda_fp16.h>
#include <math.h>
#include <stdint.h>

// Problem constants
#define NB   2
#define SEQ  2048
#define HID  4096
#define NH   32
#define NKV  8
#define HD   128
#define QKVO ((NH + 2*NKV)*HD)   // 6144
#define MTOK (NB*SEQ)            // 4096

// Scratch
__device__ float g_qkv[(size_t)MTOK * QKVO];
__device__ __half g_ah[(size_t)MTOK * HID];
__device__ __half g_wh[(size_t)QKVO * HID];
__device__ __half g_who[(size_t)HID * HID];
__device__ __half g_qhh[(size_t)NB * NH * SEQ * HD];
__device__ __half g_qll[(size_t)NB * NH * SEQ * HD];
__device__ __half g_kk[(size_t)NB * NKV * SEQ * HD];
__device__ __half g_vv[(size_t)NB * NKV * SEQ * HD];
__device__ float2 g_rope[(size_t)SEQ * 64];

// ===========================================================================
// Low-level helpers
// ===========================================================================
__device__ __forceinline__ uint32_t smem_to_u32(const void* p) {
    uint32_t a;
    asm("{ .reg .u64 t; cvta.to.shared.u64 t, %1; cvt.u32.u64 %0, t; }" : "=r"(a) : "l"(p));
    return a;
}
__device__ __forceinline__ void ldsm_x4(uint32_t& r0, uint32_t& r1, uint32_t& r2,
                                        uint32_t& r3, uint32_t addr) {
    asm volatile("ldmatrix.sync.aligned.m8n8.x4.shared.b16 {%0,%1,%2,%3}, [%4];"
                 : "=r"(r0), "=r"(r1), "=r"(r2), "=r"(r3) : "r"(addr));
}
__device__ __forceinline__ void ldsm_x4_t(uint32_t& r0, uint32_t& r1, uint32_t& r2,
                                          uint32_t& r3, uint32_t addr) {
    asm volatile("ldmatrix.sync.aligned.m8n8.x4.trans.shared.b16 {%0,%1,%2,%3}, [%4];"
                 : "=r"(r0), "=r"(r1), "=r"(r2), "=r"(r3) : "r"(addr));
}
__device__ __forceinline__ void mma_fp16(float* c, uint32_t a0, uint32_t a1,
                                         uint32_t a2, uint32_t a3,
                                         uint32_t b0, uint32_t b1) {
    asm volatile(
        "mma.sync.aligned.m16n8k16.row.col.f32.f16.f16.f32 "
        "{%0,%1,%2,%3}, {%4,%5,%6,%7}, {%8,%9}, {%0,%1,%2,%3};"
        : "+f"(c[0]), "+f"(c[1]), "+f"(c[2]), "+f"(c[3])
        : "r"(a0), "r"(a1), "r"(a2), "r"(a3), "r"(b0), "r"(b1));
}
__device__ __forceinline__ void cpa16(uint32_t dst, const void* src) {
    asm volatile("cp.async.cg.shared.global [%0], [%1], 16;" :: "r"(dst), "l"(src));
}
#define CP_COMMIT() asm volatile("cp.async.commit_group;" ::: "memory")
#define CP_WAIT0()  asm volatile("cp.async.wait_group 0;" ::: "memory")
#define CP_WAIT1()  asm volatile("cp.async.wait_group 1;" ::: "memory")

__device__ __forceinline__ uint32_t pack2_fp16(float a, float b) {
    __half2 t = __floats2half2_rn(a, b);
    return *reinterpret_cast<uint32_t*>(&t);
}

// ===========================================================================
// RoPE table (fp64 once)
// ===========================================================================
__global__ void __launch_bounds__(256) rope_table_kernel(const int* __restrict__ positions)
{
    const int idx = blockIdx.x * 256 + threadIdx.x;
    if (idx >= SEQ * 64) return;
    const int s = idx >> 6, i = idx & 63;
    const int pos = positions[s];
    const double inv = exp(-(double)i * (9.210340371976184 / 64.0));
    double sd, cd;
    sincos((double)pos * inv, &sd, &cd);
    g_rope[idx] = make_float2((float)cd, (float)sd);
}

// ===========================================================================
// Merged conversion: hidden->ah, wqkv->wh, wo->who in one launch.
// ===========================================================================
#define N_A ((size_t)MTOK * HID)
#define N_W1 ((size_t)QKVO * HID)
#define CV1 (N_A / 4)
#define CV2 (CV1 + N_W1 / 4)
#define CVTOT (CV2 + N_A / 4)

__global__ void __launch_bounds__(256) conv_all_kernel(
    const float* __restrict__ hidden, const float* __restrict__ wqkv,
    const float* __restrict__ wo,
    __half* __restrict__ ah, __half* __restrict__ wh, __half* __restrict__ who)
{
    const size_t i = (size_t)blockIdx.x * 256 + threadIdx.x;
    if (i >= CVTOT) return;
    const float* src;
    __half* dst;
    size_t off;
    if (i < CV1)      { src = hidden; dst = ah;  off = i; }
    else if (i < CV2) { src = wqkv;   dst = wh;  off = i - CV1; }
    else              { src = wo;     dst = who; off = i - CV2; }
    float4 v = *(const float4*)(src + off * 4);
    __half h[4] = { __float2half_rn(v.x), __float2half_rn(v.y),
                    __float2half_rn(v.z), __float2half_rn(v.w) };
    *(uint2*)(dst + off * 4) = *(uint2*)h;
}

// ===========================================================================
// Shared GEMM geometry: 128B-row XOR-swizzled tiles
// ===========================================================================
#define GK 64
#define GTILE 16384                  // 128 rows * 128 B

__device__ __forceinline__ uint32_t gsw(int row, int seg) {
    return (uint32_t)(row * 128 + ((seg ^ row) & 7) * 16);
}

// ===========================================================================
// fp16x1 GEMM-NT (R12 verified): 3-stage, 2 CTAs/SM.
// ===========================================================================
#define G1STAGE (2 * GTILE)          // Ah, Bh = 32768 B
#define GEMM1_SMEM (3 * G1STAGE)     // 98304 B

__global__ void __launch_bounds__(256, 2) gemm_fp16x1_kernel(
    const __half* __restrict__ Ah, const __half* __restrict__ Bh,
    float* __restrict__ C, int M, int N, int K)
{
    extern __shared__ char smem[];
    const uint32_t sb = smem_to_u32(smem);
    const int tid  = threadIdx.x;
    const int wid  = tid >> 5;
    const int lane = tid & 31;
    const int warp_m = wid >> 2;
    const int warp_n = wid & 3;
    const int bm = blockIdx.y * 128;
    const int bn = blockIdx.x * 128;

    const __half* srcs[2] = { Ah + (size_t)bm * K, Bh + (size_t)bn * K };

    float acc[4][4][4];
#pragma unroll
    for (int i = 0; i < 4; i++)
#pragma unroll
        for (int j = 0; j < 4; j++)
#pragma unroll
            for (int r = 0; r < 4; r++) acc[i][j][r] = 0.f;

    auto prefetch = [&](int k0, int s) {
        const uint32_t base = sb + s * G1STAGE;
#pragma unroll
        for (int t = 0; t < 2; t++) {
            const __half* src = srcs[t];
            const uint32_t tb = base + t * GTILE;
#pragma unroll
            for (int i = 0; i < 4; i++) {
                const int f = tid + i * 256;        // 0..1023
                const int r = f >> 3, sg = f & 7;
                cpa16(tb + gsw(r, sg), src + (size_t)r * K + k0 + sg * 8);
            }
        }
        CP_COMMIT();
    };

    const int NC = K / GK;
    prefetch(0, 0);
    prefetch(GK, 1);

    const int a_r = lane & 15;
    const int a_h = lane >> 4;
    const int b_g = lane >> 3;
    const int b_r = lane & 7;
    const int b_jj = b_g >> 1;
    const int b_h = b_g & 1;

    for (int c = 0; c < NC; c++) {
        if (c + 1 < NC) { CP_WAIT1(); } else { CP_WAIT0(); }
        __syncthreads();
        if (c + 2 < NC) prefetch((c + 2) * GK, (c + 2) % 3);

        const uint32_t base = sb + (c % 3) * G1STAGE;
#pragma unroll
        for (int ks = 0; ks < 4; ks++) {
            uint32_t ah[4][4];
#pragma unroll
            for (int mt = 0; mt < 4; mt++) {
                const int row = warp_m * 64 + mt * 16 + a_r;
                const uint32_t off = gsw(row, ks * 2 + a_h);
                ldsm_x4(ah[mt][0], ah[mt][1], ah[mt][2], ah[mt][3], base + off);
            }
#pragma unroll
            for (int jp = 0; jp < 2; jp++) {
                const int rowb = warp_n * 32 + (jp * 2 + b_jj) * 8 + b_r;
                const uint32_t boff = gsw(rowb, ks * 2 + b_h);
                uint32_t bh0, bh1, bh2, bh3;
                ldsm_x4(bh0, bh1, bh2, bh3, base + GTILE + boff);
#pragma unroll
                for (int mt = 0; mt < 4; mt++) {
                    mma_fp16(acc[mt][jp * 2],     ah[mt][0], ah[mt][1], ah[mt][2], ah[mt][3], bh0, bh1);
                    mma_fp16(acc[mt][jp * 2 + 1], ah[mt][0], ah[mt][1], ah[mt][2], ah[mt][3], bh2, bh3);
                }
            }
        }
    }

#pragma unroll
    for (int mt = 0; mt < 4; mt++) {
        const int row = bm + warp_m * 64 + mt * 16 + (lane >> 2);
#pragma unroll
        for (int nt = 0; nt < 4; nt++) {
            const int col = bn + warp_n * 32 + nt * 8 + (lane & 3) * 2;
            float* cp0 = C + (size_t)row * N + col;
            float* cp1 = C + (size_t)(row + 8) * N + col;
            *(float2*)cp0 = make_float2(acc[mt][nt][0], acc[mt][nt][1]);
            *(float2*)cp1 = make_float2(acc[mt][nt][2], acc[mt][nt][3]);
        }
    }
}

// ---------------------------------------------------------------------------
// RMSNorm + RoPE, warp-per-head (R11 verified, unchanged).
// ---------------------------------------------------------------------------
__global__ void __launch_bounds__(256) norm_rope_split_kernel(
    const float* __restrict__ qkv,
    const float* __restrict__ qw, const float* __restrict__ kw,
    __half* __restrict__ qh, __half* __restrict__ ql,
    __half* __restrict__ kk, __half* __restrict__ vv)
{
    const int token = blockIdx.x;
    const int b = token / SEQ;
    const int s = token - b * SEQ;
    const int warp = threadIdx.x >> 5;
    const int lane = threadIdx.x & 31;
    const int head = blockIdx.y * 8 + warp;      // 0..47
    const int d0 = lane * 4;

    if (head >= NH + NKV) {                      // V: convert only
        const int kvh = head - NH - NKV;
        const float4 x = *(const float4*)(qkv + (size_t)token * QKVO
                          + (size_t)(NH + NKV) * HD + (size_t)kvh * HD + d0);
        __half h[4] = { __float2half_rn(x.x), __float2half_rn(x.y),
                        __float2half_rn(x.z), __float2half_rn(x.w) };
        *(uint2*)(vv + ((size_t)(b * NKV + kvh) * SEQ + s) * HD + d0) = *(uint2*)h;
        return;
    }

    const bool is_q = head < NH;
    const float* src = qkv + (size_t)token * QKVO
                     + (is_q ? (size_t)head * HD : (size_t)NH * HD + (size_t)(head - NH) * HD);
    const float4 x = *(const float4*)(src + d0);

    float sq = x.x * x.x + x.y * x.y + x.z * x.z + x.w * x.w;
#pragma unroll
    for (int o = 16; o > 0; o >>= 1) sq += __shfl_xor_sync(0xffffffffu, sq, o);
    const float rn = rsqrtf(sq * (1.0f / HD) + 1e-6f);

    const float4 w = *(const float4*)((is_q ? qw : kw) + d0);
    float y[4] = { x.x * rn * w.x, x.y * rn * w.y, x.z * rn * w.z, x.w * rn * w.w };
    float p[4];
#pragma unroll
    for (int j = 0; j < 4; j++) p[j] = __shfl_xor_sync(0xffffffffu, y[j], 16);

    const int i0 = d0 & 63;
    float outv[4];
#pragma unroll
    for (int j = 0; j < 4; j++) {
        const float2 cs = g_rope[(size_t)s * 64 + i0 + j];
        outv[j] = (lane < 16) ? (y[j] * cs.x - p[j] * cs.y)
                              : (y[j] * cs.x + p[j] * cs.y);
    }

    if (is_q) {
        const size_t o = ((size_t)(b * NH + head) * SEQ + s) * HD + d0;
        __half h[4], l[4];
#pragma unroll
        for (int j = 0; j < 4; j++) {
            const float v = outv[j] * 0.08838834764831843f;
            h[j] = __float2half_rn(v);
            l[j] = __float2half_rn(v - __half2float(h[j]));
        }
        *(uint2*)(qh + o) = *(uint2*)h;
        *(uint2*)(ql + o) = *(uint2*)l;
    } else {
        const size_t o = ((size_t)(b * NKV + (head - NH)) * SEQ + s) * HD + d0;
        __half h[4] = { __float2half_rn(outv[0]), __float2half_rn(outv[1]),
                        __float2half_rn(outv[2]), __float2half_rn(outv[3]) };
        *(uint2*)(kk + o) = *(uint2*)h;
    }
}

// ---------------------------------------------------------------------------
// Tensor-core causal flash attention: scores fp16x2 (Q split), P·V single fp16.
// BQ=64, 128 threads, K/V double-buffered, longest-qt-first scheduling.
// ---------------------------------------------------------------------------
#define DS 136
#define FTB (64 * DS * 2)            // 17408
#define FL_SMEM (4 * FTB)            // 69632

__global__ void __launch_bounds__(128) flash_mma_kernel(
    const __half* __restrict__ gqh, const __half* __restrict__ gql,
    const __half* __restrict__ gkk, const __half* __restrict__ gvv,
    __half* __restrict__ outh)
{
    extern __shared__ char smem[];
    const uint32_t sb = smem_to_u32(smem);

    const int qt = (int)gridDim.x - 1 - (int)blockIdx.x;   // longest first
    const int h  = blockIdx.y;
    const int b  = blockIdx.z;
    const int kvh = h >> 2;
    const int tid = threadIdx.x;
    const int wid = tid >> 5;
    const int lane = tid & 31;
    const int m0 = wid * 16;

    const __half* Qh = gqh + ((size_t)(b * NH + h) * SEQ + (size_t)qt * 64) * HD;
    const __half* Ql = gql + ((size_t)(b * NH + h) * SEQ + (size_t)qt * 64) * HD;
    const __half* K  = gkk + (size_t)(b * NKV + kvh) * SEQ * HD;
    const __half* V  = gvv + (size_t)(b * NKV + kvh) * SEQ * HD;

    auto loadtile = [&](uint32_t dst, const __half* src) {
#pragma unroll
        for (int i = 0; i < 8; i++) {
            const int f = tid + i * 128;
            const int r = f >> 4, sg = f & 15;
            cpa16(dst + (uint32_t)(r * DS + sg * 8) * 2, src + (size_t)r * HD + sg * 8);
        }
    };

    const int a_r = lane & 15, a_c = (lane >> 4) * 8;
    const int b_r = lane & 7,  b_g = lane >> 3;
    const int b_jj = b_g >> 1, b_kk = (b_g & 1) * 8;
    const int qrow = lane >> 2;
    const int qcol = (lane & 3) * 2;

    // ---- stage Q through ping/pong K buffers, hoist fragments ----
    loadtile(sb, Qh);
    loadtile(sb + 2 * FTB, Ql);
    CP_COMMIT();
    CP_WAIT0();
    __syncthreads();
    uint32_t qfh[8][4], qfl[8][4];
#pragma unroll
    for (int kb = 0; kb < 8; kb++) {
        const uint32_t aoff = (uint32_t)((m0 + a_r) * DS + kb * 16 + a_c) * 2;
        ldsm_x4(qfh[kb][0], qfh[kb][1], qfh[kb][2], qfh[kb][3], sb + aoff);
        ldsm_x4(qfl[kb][0], qfl[kb][1], qfl[kb][2], qfl[kb][3], sb + 2 * FTB + aoff);
    }
    __syncthreads();

    float o[16][4];
#pragma unroll
    for (int i = 0; i < 16; i++)
#pragma unroll
        for (int j = 0; j < 4; j++) o[i][j] = 0.f;
    float mrow[2] = {-INFINITY, -INFINITY};
    float lrow[2] = {0.f, 0.f};

    // prefetch KV tile 0 into ping
    loadtile(sb,       K);
    loadtile(sb + FTB, V);
    CP_COMMIT();

    for (int jt = 0; jt <= qt; jt++) {
        if (jt < qt) {
            const uint32_t nb = sb + ((jt + 1) & 1) * 2 * FTB;
            loadtile(nb,       K + (size_t)(jt + 1) * 64 * HD);
            loadtile(nb + FTB, V + (size_t)(jt + 1) * 64 * HD);
            CP_COMMIT();
            CP_WAIT1();
        } else {
            CP_WAIT0();
        }
        __syncthreads();

        const uint32_t sK = sb + (jt & 1) * 2 * FTB;
        const uint32_t sV = sK + FTB;

        // ---- scores = Q K^T (Q split fp16 hi/lo) ----
        float sc[8][4];
#pragma unroll
        for (int i = 0; i < 8; i++)
#pragma unroll
            for (int j = 0; j < 4; j++) sc[i][j] = 0.f;

#pragma unroll
        for (int kb = 0; kb < 8; kb++) {
#pragma unroll
            for (int np = 0; np < 4; np++) {
                const uint32_t boff =
                    (uint32_t)(((np * 2 + b_jj) * 8 + b_r) * DS + kb * 16 + b_kk) * 2;
                uint32_t k0, k1, k2, k3;
                ldsm_x4(k0, k1, k2, k3, sK + boff);
                float* c0 = sc[np * 2];
                float* c1 = sc[np * 2 + 1];
                mma_fp16(c0, qfh[kb][0], qfh[kb][1], qfh[kb][2], qfh[kb][3], k0, k1);
                mma_fp16(c1, qfh[kb][0], qfh[kb][1], qfh[kb][2], qfh[kb][3], k2, k3);
                mma_fp16(c0, qfl[kb][0], qfl[kb][1], qfl[kb][2], qfl[kb][3], k0, k1);
                mma_fp16(c1, qfl[kb][0], qfl[kb][1], qfl[kb][2], qfl[kb][3], k2, k3);
            }
        }

        if (jt == qt) {
            const int r0 = m0 + qrow, r1 = r0 + 8;
#pragma unroll
            for (int nt = 0; nt < 8; nt++) {
                const int col = nt * 8 + qcol;
                if (col > r0)     sc[nt][0] = -INFINITY;
                if (col + 1 > r0) sc[nt][1] = -INFINITY;
                if (col > r1)     sc[nt][2] = -INFINITY;
                if (col + 1 > r1) sc[nt][3] = -INFINITY;
            }
        }

        float mx0 = -INFINITY, mx1 = -INFINITY;
#pragma unroll
        for (int nt = 0; nt < 8; nt++) {
            mx0 = fmaxf(mx0, fmaxf(sc[nt][0], sc[nt][1]));
            mx1 = fmaxf(mx1, fmaxf(sc[nt][2], sc[nt][3]));
        }
        mx0 = fmaxf(mx0, __shfl_xor_sync(0xffffffffu, mx0, 1));
        mx0 = fmaxf(mx0, __shfl_xor_sync(0xffffffffu, mx0, 2));
        mx1 = fmaxf(mx1, __shfl_xor_sync(0xffffffffu, mx1, 1));
        mx1 = fmaxf(mx1, __shfl_xor_sync(0xffffffffu, mx1, 2));
        const float mn0 = fmaxf(mrow[0], mx0);
        const float mn1 = fmaxf(mrow[1], mx1);
        const float cr0 = __expf(mrow[0] - mn0);
        const float cr1 = __expf(mrow[1] - mn1);
        mrow[0] = mn0; mrow[1] = mn1;

        float s0 = 0.f, s1 = 0.f;
#pragma unroll
        for (int nt = 0; nt < 8; nt++) {
            sc[nt][0] = __expf(sc[nt][0] - mn0); s0 += sc[nt][0];
            sc[nt][1] = __expf(sc[nt][1] - mn0); s0 += sc[nt][1];
            sc[nt][2] = __expf(sc[nt][2] - mn1); s1 += sc[nt][2];
            sc[nt][3] = __expf(sc[nt][3] - mn1); s1 += sc[nt][3];
        }
        s0 += __shfl_xor_sync(0xffffffffu, s0, 1);
        s0 += __shfl_xor_sync(0xffffffffu, s0, 2);
        s1 += __shfl_xor_sync(0xffffffffu, s1, 1);
        s1 += __shfl_xor_sync(0xffffffffu, s1, 2);
        lrow[0] = lrow[0] * cr0 + s0;
        lrow[1] = lrow[1] * cr1 + s1;

#pragma unroll
        for (int nt = 0; nt < 16; nt++) {
            o[nt][0] *= cr0; o[nt][1] *= cr0;
            o[nt][2] *= cr1; o[nt][3] *= cr1;
        }

        // ---- out += P V (P single fp16) ----
#pragma unroll
        for (int kc = 0; kc < 4; kc++) {
            const uint32_t ph0 = pack2_fp16(sc[kc * 2][0],     sc[kc * 2][1]);
            const uint32_t ph1 = pack2_fp16(sc[kc * 2][2],     sc[kc * 2][3]);
            const uint32_t ph2 = pack2_fp16(sc[kc * 2 + 1][0], sc[kc * 2 + 1][1]);
            const uint32_t ph3 = pack2_fp16(sc[kc * 2 + 1][2], sc[kc * 2 + 1][3]);

#pragma unroll
            for (int npair = 0; npair < 8; npair++) {
                const uint32_t voff =
                    (uint32_t)((kc * 16 + a_r) * DS + npair * 16 + a_c) * 2;
                uint32_t v0, v1, v2, v3;
                ldsm_x4_t(v0, v1, v2, v3, sV + voff);
                mma_fp16(o[npair * 2],     ph0, ph1, ph2, ph3, v0, v1);
                mma_fp16(o[npair * 2 + 1], ph0, ph1, ph2, ph3, v2, v3);
            }
        }
        __syncthreads();
    }

    const float iv0 = 1.f / lrow[0];
    const float iv1 = 1.f / lrow[1];
    const size_t t0 = (size_t)b * SEQ + (size_t)qt * 64 + m0 + qrow;
    const size_t t1 = t0 + 8;
#pragma unroll
    for (int nt = 0; nt < 16; nt++) {
        const int col = h * HD + nt * 8 + qcol;
        *(__half2*)(outh + t0 * HID + col) =
            __floats2half2_rn(o[nt][0] * iv0, o[nt][1] * iv0);
        *(__half2*)(outh + t1 * HID + col) =
            __floats2half2_rn(o[nt][2] * iv1, o[nt][3] * iv1);
    }
}

// ---------------------------------------------------------------------------
extern "C" void kernel_launch(void* const* d_in, const int* in_sizes, int n_in,
                              void* d_out, int out_size)
{
    const float* hidden    = (const float*)d_in[0];
    const int*   positions = (const int*)d_in[1];
    const float* wqkv      = (const float*)d_in[2];
    const float* qnw       = (const float*)d_in[3];
    const float* knw       = (const float*)d_in[4];
    const float* wo        = (const float*)d_in[5];
    float* out = (float*)d_out;

    float* qkv;
    __half *ah, *wh, *who, *qh, *ql, *kk, *vv;
    cudaGetSymbolAddress((void**)&qkv, g_qkv);
    cudaGetSymbolAddress((void**)&ah, g_ah);
    cudaGetSymbolAddress((void**)&wh, g_wh);
    cudaGetSymbolAddress((void**)&who, g_who);
    cudaGetSymbolAddress((void**)&qh, g_qhh);
    cudaGetSymbolAddress((void**)&ql, g_qll);
    cudaGetSymbolAddress((void**)&kk, g_kk);
    cudaGetSymbolAddress((void**)&vv, g_vv);

    cudaFuncSetAttribute(gemm_fp16x1_kernel,
                         cudaFuncAttributeMaxDynamicSharedMemorySize, GEMM1_SMEM);
    cudaFuncSetAttribute(flash_mma_kernel,
                         cudaFuncAttributeMaxDynamicSharedMemorySize, FL_SMEM);

    // 0) RoPE table
    rope_table_kernel<<<(SEQ * 64 + 255) / 256, 256>>>(positions);

    // 1) merged conversions: hidden->ah, wqkv->wh, wo->who
    conv_all_kernel<<<(unsigned)((CVTOT + 255) / 256), 256>>>(
        hidden, wqkv, wo, ah, wh, who);

    // 2) QKV projection (fp16x1)
    dim3 g1(QKVO / 128, MTOK / 128);
    gemm_fp16x1_kernel<<<g1, 256, GEMM1_SMEM>>>(ah, wh, qkv, MTOK, QKVO, HID);

    // 3) RMSNorm + RoPE, warp-per-head
    dim3 g2(MTOK, 6);
    norm_rope_split_kernel<<<g2, 256>>>(qkv, qnw, knw, qh, ql, kk, vv);

    // 4) Flash attention (scores fp16x2, PV fp16x1) -> fp16 attn
    dim3 g3(SEQ / 64, NH, NB);
    flash_mma_kernel<<<g3, 128, FL_SMEM>>>(qh, ql, kk, vv, ah);

    // 5) output projection (fp16x1)
    dim3 g4(HID / 128, MTOK / 128);
    gemm_fp16x1_kernel<<<g4, 256, GEMM1_SMEM>>>(ah, who, out, MTOK, HID, HID);
}